// round 16
// baseline (speedup 1.0000x reference)
#include <cuda_runtime.h>
#include <math.h>

// ---------------------------------------------------------------------------
// Problem dimensions (fixed by setup_inputs)
// ---------------------------------------------------------------------------
namespace cfg {
constexpr int B  = 128;
constexpr int H0 = 200, W0 = 128, C0 = 6;
constexpr int C1 = 8;
constexpr int H1 = 100, W1 = 64;
constexpr int C2 = 16;
constexpr int H2 = 20,  W2 = 32;
constexpr int C3 = 32;
constexpr int H3 = 4,   W3 = 16;
constexpr int LAT = 4, HID = 16, NPAR = 11, NT = 10;
constexpr float BOUND = 5.0f;
constexpr float LOG2PI = 1.8378770664093453f;

constexpr long OUT_N   = (long)B * C0 * H0 * W0;
constexpr long MU_OFF  = OUT_N;
constexpr long MU_N    = (long)B * H3 * W3 * LAT;
constexpr long LV_OFF  = MU_OFF + MU_N;
constexpr long KLD_OFF = LV_OFF + MU_N;
constexpr long ZF_OFF  = KLD_OFF + B;
}
using namespace cfg;

// ---------------------------------------------------------------------------
// Packed f32x2 FMA helpers (Blackwell FFMA2)
// ---------------------------------------------------------------------------
__device__ __forceinline__ unsigned long long pack2(float lo, float hi)
{
    unsigned long long r;
    asm("mov.b64 %0, {%1, %2};" : "=l"(r) : "f"(lo), "f"(hi));
    return r;
}
__device__ __forceinline__ void unpack2(unsigned long long v, float& lo, float& hi)
{
    asm("mov.b64 {%0, %1}, %2;" : "=f"(lo), "=f"(hi) : "l"(v));
}
__device__ __forceinline__ unsigned long long ffma2(unsigned long long a,
                                                    unsigned long long b,
                                                    unsigned long long c)
{
    unsigned long long d;
    asm("fma.rn.f32x2 %0, %1, %2, %3;" : "=l"(d) : "l"(a), "l"(b), "l"(c));
    return d;
}

template <int CO>
__device__ __forceinline__ void fma_row2(const float* __restrict__ wrow, float v,
                                         unsigned long long* acc)
{
    unsigned long long vv = pack2(v, v);
#pragma unroll
    for (int g = 0; g < CO / 2; g++) {
        unsigned long long w = *reinterpret_cast<const unsigned long long*>(wrow + 2 * g);
        acc[g] = ffma2(vv, w, acc[g]);
    }
}

template <int P>
__device__ __forceinline__ void store_px(float* dst, const float* v)
{
    if constexpr (P == 4) {
        *reinterpret_cast<float4*>(dst) = make_float4(v[0], v[1], v[2], v[3]);
    } else if constexpr (P == 2) {
        *reinterpret_cast<float2*>(dst) = make_float2(v[0], v[1]);
    } else {
        dst[0] = v[0];
    }
}

template <int N2>
__device__ __forceinline__ float dot_packed(const float* __restrict__ row,
                                            const unsigned long long* xp, float bias)
{
    unsigned long long acc = pack2(bias, 0.0f);
    const unsigned long long* r2 = reinterpret_cast<const unsigned long long*>(row);
#pragma unroll
    for (int k = 0; k < N2; k++) acc = ffma2(xp[k], r2[k], acc);
    float lo, hi;
    unpack2(acc, lo, hi);
    return lo + hi;
}

// ---------------------------------------------------------------------------
// Static device scratch
// ---------------------------------------------------------------------------
__device__ float g_p1[(long)B * C1 * H1 * W1];
__device__ float g_p2[(long)B * C2 * H2 * W2];
__device__ float g_y3[(long)B * C3 * H2 * W2];
__device__ float g_dec[(long)B * C3 * H3 * W3];
__device__ float g_d1[(long)B * C3 * H2 * W2];
__device__ float g_c4[(long)B * C2 * H2 * W2];
__device__ float g_c5[(long)B * C1 * H1 * W1];
__device__ float g_kldp[(long)B * 2];
__device__ unsigned char g_m0[(long)B * H0 * W0];
__device__ unsigned char g_m1[(long)B * H1 * W1];
__device__ unsigned char g_m2[(long)B * H2 * W2];

// ---------------------------------------------------------------------------
// Fused encoder stage 1: mask0 + conv1(3x3, 6->8) + lrelu + maxpool 2x2 + m1
// ---------------------------------------------------------------------------
constexpr int E1H = 16, E1W = 32, E1T = 128;

__global__ __launch_bounds__(E1T) void enc1_kernel(
    const float* __restrict__ x, const float* __restrict__ w1,
    const float* __restrict__ b1, float* __restrict__ p1,
    unsigned char* __restrict__ m0, unsigned char* __restrict__ m1)
{
    __shared__ __align__(16) float xs[C0][E1H + 2][E1W + 2];
    __shared__ __align__(16) float cs[C1][E1H][E1W];
    __shared__ unsigned char ms[E1H][E1W];
    __shared__ __align__(16) float ws[9 * C0 * C1];
    __shared__ float bs[C1];

    const int b  = blockIdx.z;
    const int h0 = blockIdx.y * E1H;
    const int w0 = blockIdx.x * E1W;
    const int tid = threadIdx.x;

    for (int i = tid; i < 9 * C0 * C1; i += E1T) ws[i] = w1[i];
    if (tid < C1) bs[tid] = b1[tid];

    for (int i = tid; i < C0 * (E1H + 2) * (E1W + 2); i += E1T) {
        int lw = i % (E1W + 2);
        int r  = i / (E1W + 2);
        int lh = r % (E1H + 2);
        int c  = r / (E1H + 2);
        int gh = h0 + lh - 1, gw = w0 + lw - 1;
        float v = 0.0f;
        if (gh >= 0 && gh < H0 && gw >= 0 && gw < W0)
            v = x[(((long)b * C0 + c) * H0 + gh) * W0 + gw];
        xs[c][lh][lw] = v;
    }
    __syncthreads();

    {
        const int pix = tid * 4;
        const int lh = pix / E1W, lw = pix % E1W;
        const int gh = h0 + lh, gw = w0 + lw;

        bool a[4];
        bool anyA = false;
#pragma unroll
        for (int p = 0; p < 4; p++) {
            bool v = false;
            if (gh < H0) {
#pragma unroll
                for (int c = 0; c < C0; c++)
                    v = v || (xs[c][lh + 1][lw + 1 + p] != 0.0f);
            }
            a[p] = v;
            anyA = anyA || v;
            ms[lh][lw + p] = v ? 1 : 0;
        }
        if (gh < H0) {
            uchar4 mq = make_uchar4(a[0] ? 1 : 0, a[1] ? 1 : 0, a[2] ? 1 : 0, a[3] ? 1 : 0);
            *reinterpret_cast<uchar4*>(m0 + ((long)b * H0 + gh) * W0 + gw) = mq;
        }

        unsigned long long acc[4][C1 / 2];
#pragma unroll
        for (int p = 0; p < 4; p++)
#pragma unroll
            for (int g = 0; g < C1 / 2; g++)
                acc[p][g] = pack2(bs[2 * g], bs[2 * g + 1]);

        if (anyA) {
#pragma unroll
            for (int kh = 0; kh < 3; kh++)
#pragma unroll
                for (int ci = 0; ci < C0; ci++) {
                    float v[6];
#pragma unroll
                    for (int q = 0; q < 6; q++) v[q] = xs[ci][lh + kh][lw + q];
#pragma unroll
                    for (int kw = 0; kw < 3; kw++) {
                        const float* wrow = ws + ((kh * 3 + kw) * C0 + ci) * C1;
#pragma unroll
                        for (int p = 0; p < 4; p++)
                            fma_row2<C1>(wrow, v[kw + p], acc[p]);
                    }
                }
        }
#pragma unroll
        for (int g = 0; g < C1 / 2; g++)
#pragma unroll
            for (int p = 0; p < 4; p++) {
                float u0, u1;
                unpack2(acc[p][g], u0, u1);
                u0 = u0 > 0.0f ? u0 : 0.01f * u0;
                u1 = u1 > 0.0f ? u1 : 0.01f * u1;
                cs[2 * g][lh][lw + p]     = a[p] ? u0 : 0.0f;
                cs[2 * g + 1][lh][lw + p] = a[p] ? u1 : 0.0f;
            }
    }
    __syncthreads();

    {
        const int pw = tid % (E1W / 2), ph = tid / (E1W / 2);
        const int gph = h0 / 2 + ph, gpw = w0 / 2 + pw;
        if (gph < H1) {
            bool m00 = ms[2 * ph][2 * pw],     m01 = ms[2 * ph][2 * pw + 1];
            bool m10 = ms[2 * ph + 1][2 * pw], m11 = ms[2 * ph + 1][2 * pw + 1];
            bool any = m00 || m01 || m10 || m11;
            m1[((long)b * H1 + gph) * W1 + gpw] = any ? 1 : 0;
#pragma unroll
            for (int c = 0; c < C1; c++) {
                float v = -1e30f;
                if (m00) v = fmaxf(v, cs[c][2 * ph][2 * pw]);
                if (m01) v = fmaxf(v, cs[c][2 * ph][2 * pw + 1]);
                if (m10) v = fmaxf(v, cs[c][2 * ph + 1][2 * pw]);
                if (m11) v = fmaxf(v, cs[c][2 * ph + 1][2 * pw + 1]);
                p1[(((long)b * C1 + c) * H1 + gph) * W1 + gpw] = any ? v : 0.0f;
            }
        }
    }
}

// ---------------------------------------------------------------------------
// Fused conv2 (3x3, 8->16) + lrelu + maxpool 5x2 -> p2, m2
// ---------------------------------------------------------------------------
constexpr int P2TH = 10, P2TW = 32, P2T = 160;

__global__ __launch_bounds__(P2T) void conv2pool_kernel(
    const float* __restrict__ in, const unsigned char* __restrict__ m1,
    const float* __restrict__ wgt, const float* __restrict__ bias,
    float* __restrict__ p2, unsigned char* __restrict__ m2)
{
    __shared__ __align__(16) float xs[C1][P2TH + 2][P2TW + 2];
    __shared__ __align__(16) float cs[C2][P2TH][P2TW];
    __shared__ unsigned char ms[P2TH][P2TW];
    __shared__ __align__(16) float ws[9 * C1 * C2];
    __shared__ float bs[C2];

    const int b  = blockIdx.z;
    const int h0 = blockIdx.y * P2TH;
    const int w0 = blockIdx.x * P2TW;
    const int tid = threadIdx.x;

    for (int i = tid; i < 9 * C1 * C2; i += P2T) ws[i] = wgt[i];
    if (tid < C2) bs[tid] = bias[tid];

    for (int i = tid; i < C1 * (P2TH + 2) * (P2TW + 2); i += P2T) {
        int lw = i % (P2TW + 2);
        int r  = i / (P2TW + 2);
        int lh = r % (P2TH + 2);
        int c  = r / (P2TH + 2);
        int gh = h0 + lh - 1, gw = w0 + lw - 1;
        float v = 0.0f;
        if (gh >= 0 && gh < H1 && gw >= 0 && gw < W1)
            v = in[(((long)b * C1 + c) * H1 + gh) * W1 + gw];
        xs[c][lh][lw] = v;
    }
    __syncthreads();

    {
        const int pix = tid * 2;
        const int lh = pix / P2TW, lw = pix % P2TW;
        const int gh = h0 + lh, gw = w0 + lw;

        bool a[2];
        bool anyA = false;
#pragma unroll
        for (int p = 0; p < 2; p++) {
            a[p] = m1[((long)b * H1 + gh) * W1 + gw + p] != 0;
            anyA = anyA || a[p];
            ms[lh][lw + p] = a[p] ? 1 : 0;
        }

        unsigned long long acc[2][C2 / 2];
#pragma unroll
        for (int p = 0; p < 2; p++)
#pragma unroll
            for (int g = 0; g < C2 / 2; g++)
                acc[p][g] = pack2(bs[2 * g], bs[2 * g + 1]);

        if (anyA) {
#pragma unroll
            for (int kh = 0; kh < 3; kh++)
#pragma unroll
                for (int ci = 0; ci < C1; ci++) {
                    float v[4];
#pragma unroll
                    for (int q = 0; q < 4; q++) v[q] = xs[ci][lh + kh][lw + q];
#pragma unroll
                    for (int kw = 0; kw < 3; kw++) {
                        const float* wrow = ws + ((kh * 3 + kw) * C1 + ci) * C2;
#pragma unroll
                        for (int p = 0; p < 2; p++)
                            fma_row2<C2>(wrow, v[kw + p], acc[p]);
                    }
                }
        }
#pragma unroll
        for (int g = 0; g < C2 / 2; g++)
#pragma unroll
            for (int p = 0; p < 2; p++) {
                float u0, u1;
                unpack2(acc[p][g], u0, u1);
                u0 = u0 > 0.0f ? u0 : 0.01f * u0;
                u1 = u1 > 0.0f ? u1 : 0.01f * u1;
                cs[2 * g][lh][lw + p]     = a[p] ? u0 : 0.0f;
                cs[2 * g + 1][lh][lw + p] = a[p] ? u1 : 0.0f;
            }
    }
    __syncthreads();

    const int POOL_PX = (P2TH / 5) * (P2TW / 2);  // 32
    for (int i = tid; i < POOL_PX * C2; i += P2T) {
        int c  = i / POOL_PX;
        int px = i % POOL_PX;
        int ph = px / (P2TW / 2), pw = px % (P2TW / 2);
        bool any = false;
        float v = -1e30f;
#pragma unroll
        for (int ii = 0; ii < 5; ii++)
#pragma unroll
            for (int jj = 0; jj < 2; jj++) {
                if (ms[ph * 5 + ii][pw * 2 + jj]) {
                    any = true;
                    v = fmaxf(v, cs[c][ph * 5 + ii][pw * 2 + jj]);
                }
            }
        int gph = h0 / 5 + ph, gpw = w0 / 2 + pw;
        p2[(((long)b * C2 + c) * H2 + gph) * W2 + gpw] = any ? v : 0.0f;
        if (c == 0) m2[((long)b * H2 + gph) * W2 + gpw] = any ? 1 : 0;
    }
}

// ---------------------------------------------------------------------------
// Tiled 3x3 SAME conv (generic, dense mask), packed FFMA2, vector stores
// ---------------------------------------------------------------------------
template <int CI, int CO, int TH, int TW, int THREADS, bool LRELU>
__global__ __launch_bounds__(THREADS) void conv_tiled_kernel(
    const float* __restrict__ in, const unsigned char* __restrict__ mask,
    const float* __restrict__ wgt, const float* __restrict__ bias,
    float* __restrict__ out, int H, int W)
{
    constexpr int P = (TH * TW) / THREADS;
    static_assert(P == 1 || P == 2 || P == 4, "P must be 1/2/4");
    static_assert(CO % 2 == 0, "CO must be even");
    __shared__ __align__(16) float xs[CI][TH + 2][TW + 2];
    __shared__ __align__(16) float ws[9 * CI * CO];
    __shared__ float bs[CO];

    const int b  = blockIdx.z;
    const int h0 = blockIdx.y * TH;
    const int w0 = blockIdx.x * TW;
    const int tid = threadIdx.x;

    for (int i = tid; i < 9 * CI * CO; i += THREADS) ws[i] = wgt[i];
    if (tid < CO) bs[tid] = bias[tid];

    for (int i = tid; i < CI * (TH + 2) * (TW + 2); i += THREADS) {
        int lw = i % (TW + 2);
        int r  = i / (TW + 2);
        int lh = r % (TH + 2);
        int c  = r / (TH + 2);
        int gh = h0 + lh - 1, gw = w0 + lw - 1;
        float v = 0.0f;
        if (gh >= 0 && gh < H && gw >= 0 && gw < W)
            v = in[(((long)b * CI + c) * H + gh) * W + gw];
        xs[c][lh][lw] = v;
    }
    __syncthreads();

    const int pix = tid * P;
    const int lh = pix / TW, lw = pix % TW;
    const int gh = h0 + lh, gw = w0 + lw;

    bool a[P];
    bool anyA = false;
#pragma unroll
    for (int p = 0; p < P; p++) {
        a[p] = (gh < H) ? (mask[((long)b * H + gh) * W + gw + p] != 0) : false;
        anyA = anyA || a[p];
    }

    unsigned long long acc[P][CO / 2];
#pragma unroll
    for (int p = 0; p < P; p++)
#pragma unroll
        for (int g = 0; g < CO / 2; g++) acc[p][g] = pack2(bs[2 * g], bs[2 * g + 1]);

    if (anyA) {
#pragma unroll
        for (int kh = 0; kh < 3; kh++)
#pragma unroll
            for (int ci = 0; ci < CI; ci++) {
                float v[P + 2];
#pragma unroll
                for (int q = 0; q < P + 2; q++) v[q] = xs[ci][lh + kh][lw + q];
#pragma unroll
                for (int kw = 0; kw < 3; kw++) {
                    const float* wrow = ws + ((kh * 3 + kw) * CI + ci) * CO;
#pragma unroll
                    for (int p = 0; p < P; p++)
                        fma_row2<CO>(wrow, v[kw + p], acc[p]);
                }
            }
    }
    if (gh < H) {
#pragma unroll
        for (int g = 0; g < CO / 2; g++) {
            float lo[P], hi[P];
#pragma unroll
            for (int p = 0; p < P; p++) {
                float u0, u1;
                unpack2(acc[p][g], u0, u1);
                if (LRELU) {
                    u0 = u0 > 0.0f ? u0 : 0.01f * u0;
                    u1 = u1 > 0.0f ? u1 : 0.01f * u1;
                }
                lo[p] = a[p] ? u0 : 0.0f;
                hi[p] = a[p] ? u1 : 0.0f;
            }
            store_px<P>(&out[(((long)b * CO + 2 * g) * H + gh) * W + gw], lo);
            store_px<P>(&out[(((long)b * CO + 2 * g + 1) * H + gh) * W + gw], hi);
        }
    }
}

// ---------------------------------------------------------------------------
// Fused decoder stage: invconv (KHxKW upsample, CI->CM) + 3x3 conv (CM->CO)
// ---------------------------------------------------------------------------
template <int CI, int CM, int CO, int KH, int KW, int TH, int TW, int THREADS>
__global__ __launch_bounds__(THREADS) void dec_fused_kernel(
    const float* __restrict__ in, const unsigned char* __restrict__ mo,
    const float* __restrict__ u, const float* __restrict__ bu,
    const float* __restrict__ wgt, const float* __restrict__ bias,
    float* __restrict__ out, int Hi, int Wi)
{
    constexpr int P = (TH * TW) / THREADS;
    static_assert(P == 1 || P == 2 || P == 4, "P must be 1/2/4");
    static_assert(CM % 2 == 0 && CO % 2 == 0, "CM/CO must be even");
    const int Ho = Hi * KH, Wo = Wi * KW;

    __shared__ __align__(16) float us_[CM][TH + 2][TW + 2];
    __shared__ unsigned char msk[(TH + 2) * (TW + 2)];
    __shared__ __align__(16) float su[KH * KW * CI * CM];
    __shared__ __align__(16) float ws[9 * CM * CO];
    __shared__ float sbu[CM], bs[CO];

    const int b  = blockIdx.z;
    const int h0 = blockIdx.y * TH;
    const int w0 = blockIdx.x * TW;
    const int tid = threadIdx.x;

    for (int i = tid; i < KH * KW * CI * CM; i += THREADS) su[i] = u[i];
    for (int i = tid; i < 9 * CM * CO; i += THREADS) ws[i] = wgt[i];
    if (tid < CM) sbu[tid] = bu[tid];
    if (tid < CO) bs[tid] = bias[tid];
    __syncthreads();

    for (int i = tid; i < (TH + 2) * (TW + 2); i += THREADS) {
        int lw = i % (TW + 2), lh = i / (TW + 2);
        int gh = h0 + lh - 1, gw = w0 + lw - 1;
        bool act = false;
        if (gh >= 0 && gh < Ho && gw >= 0 && gw < Wo)
            act = mo[((long)b * Ho + gh) * Wo + gw] != 0;
        unsigned long long val[CM / 2];
        if (act) {
#pragma unroll
            for (int g = 0; g < CM / 2; g++) val[g] = pack2(sbu[2 * g], sbu[2 * g + 1]);
            int hi = gh / KH, ii = gh % KH;
            int wi = gw / KW, jj = gw % KW;
            const float* ub = su + ((ii * KW + jj) * CI) * CM;
#pragma unroll
            for (int ci = 0; ci < CI; ci++) {
                float v = in[(((long)b * CI + ci) * Hi + hi) * Wi + wi];
                fma_row2<CM>(ub + ci * CM, v, val);
            }
        } else {
#pragma unroll
            for (int g = 0; g < CM / 2; g++) val[g] = 0ull;
        }
        msk[i] = act ? 1 : 0;
#pragma unroll
        for (int g = 0; g < CM / 2; g++) {
            float u0, u1;
            unpack2(val[g], u0, u1);
            us_[2 * g][lh][lw]     = u0;
            us_[2 * g + 1][lh][lw] = u1;
        }
    }
    __syncthreads();

    const int pix = tid * P;
    const int lh = pix / TW, lw = pix % TW;
    const int gh = h0 + lh, gw = w0 + lw;

    bool a[P];
    bool anyA = false;
#pragma unroll
    for (int p = 0; p < P; p++) {
        a[p] = (gh < Ho) && (msk[(lh + 1) * (TW + 2) + lw + 1 + p] != 0);
        anyA = anyA || a[p];
    }

    unsigned long long acc[P][CO / 2];
#pragma unroll
    for (int p = 0; p < P; p++)
#pragma unroll
        for (int g = 0; g < CO / 2; g++) acc[p][g] = pack2(bs[2 * g], bs[2 * g + 1]);

    if (anyA) {
#pragma unroll
        for (int kh = 0; kh < 3; kh++)
#pragma unroll
            for (int ci = 0; ci < CM; ci++) {
                float v[P + 2];
#pragma unroll
                for (int q = 0; q < P + 2; q++) v[q] = us_[ci][lh + kh][lw + q];
#pragma unroll
                for (int kw = 0; kw < 3; kw++) {
                    const float* wrow = ws + ((kh * 3 + kw) * CM + ci) * CO;
#pragma unroll
                    for (int p = 0; p < P; p++)
                        fma_row2<CO>(wrow, v[kw + p], acc[p]);
                }
            }
    }
    if (gh < Ho) {
#pragma unroll
        for (int g = 0; g < CO / 2; g++) {
            float lo[P], hi[P];
#pragma unroll
            for (int p = 0; p < P; p++) {
                float u0, u1;
                unpack2(acc[p][g], u0, u1);
                lo[p] = a[p] ? u0 : 0.0f;
                hi[p] = a[p] ? u1 : 0.0f;
            }
            store_px<P>(&out[(((long)b * CO + 2 * g) * Ho + gh) * Wo + gw], lo);
            store_px<P>(&out[(((long)b * CO + 2 * g + 1) * Ho + gh) * Wo + gw], hi);
        }
    }
}

// ---------------------------------------------------------------------------
// Standalone inverse conv (dec1 only), packed FFMA2
// ---------------------------------------------------------------------------
template <int CI, int CO, int KH, int KW, int THREADS>
__global__ __launch_bounds__(THREADS) void invconv_kernel(
    const float* __restrict__ in, const unsigned char* __restrict__ mask,
    const float* __restrict__ wgt, const float* __restrict__ bias,
    float* __restrict__ out, int Hi, int Wi)
{
    static_assert(CO % 2 == 0, "CO even");
    __shared__ __align__(16) float ws[KH * KW * CI * CO];
    __shared__ float bs[CO];
    for (int i = threadIdx.x; i < KH * KW * CI * CO; i += THREADS) ws[i] = wgt[i];
    for (int i = threadIdx.x; i < CO; i += THREADS) bs[i] = bias[i];
    __syncthreads();

    const int Ho = Hi * KH, Wo = Wi * KW;
    long idx = (long)blockIdx.x * blockDim.x + threadIdx.x;
    long total = (long)B * Ho * Wo;
    if (idx >= total) return;
    int wo = (int)(idx % Wo);
    long t = idx / Wo;
    int ho = (int)(t % Ho);
    int b  = (int)(t / Ho);

    long oplane = (long)Ho * Wo;
    unsigned long long acc[CO / 2];
    bool act = mask[idx] != 0;
    if (act) {
#pragma unroll
        for (int g = 0; g < CO / 2; g++) acc[g] = pack2(bs[2 * g], bs[2 * g + 1]);
        int hi = ho / KH, i = ho % KH;
        int wi = wo / KW, j = wo % KW;
        const float* ws2 = ws + (i * KW + j) * CI * CO;
        long iplane = (long)Hi * Wi;
        const float* inb = in + (long)b * CI * iplane + (long)hi * Wi + wi;
#pragma unroll
        for (int ci = 0; ci < CI; ci++) {
            float v = inb[(long)ci * iplane];
            fma_row2<CO>(ws2 + ci * CO, v, acc);
        }
    } else {
#pragma unroll
        for (int g = 0; g < CO / 2; g++) acc[g] = 0ull;
    }
    float* outb = out + (long)b * CO * oplane + (long)ho * Wo + wo;
#pragma unroll
    for (int g = 0; g < CO / 2; g++) {
        float u0, u1;
        unpack2(acc[g], u0, u1);
        outb[(long)(2 * g) * oplane]     = u0;
        outb[(long)(2 * g + 1) * oplane] = u1;
    }
}

// ---------------------------------------------------------------------------
// RQS spline — fast MUFU intrinsics
// ---------------------------------------------------------------------------
__device__ __forceinline__ float softplus_f(float x)
{
    return fmaxf(x, 0.0f) + __logf(1.0f + __expf(-fabsf(x)));
}

__device__ __forceinline__ float rqs_scalar(float x, const float* uw, const float* uh,
                                            const float* ud, float* ld_out)
{
    float mw = fmaxf(fmaxf(uw[0], uw[1]), fmaxf(uw[2], uw[3]));
    float e0 = __expf(uw[0] - mw), e1 = __expf(uw[1] - mw), e2 = __expf(uw[2] - mw), e3 = __expf(uw[3] - mw);
    float inv = __fdividef(2.0f * BOUND, e0 + e1 + e2 + e3);
    float xk[5];
    xk[0] = -BOUND;
    xk[1] = xk[0] + e0 * inv;
    xk[2] = xk[1] + e1 * inv;
    xk[3] = xk[2] + e2 * inv;
    xk[4] = xk[3] + e3 * inv;

    float mh = fmaxf(fmaxf(uh[0], uh[1]), fmaxf(uh[2], uh[3]));
    float f0 = __expf(uh[0] - mh), f1 = __expf(uh[1] - mh), f2 = __expf(uh[2] - mh), f3 = __expf(uh[3] - mh);
    float invh = __fdividef(2.0f * BOUND, f0 + f1 + f2 + f3);
    float yk[5];
    yk[0] = -BOUND;
    yk[1] = yk[0] + f0 * invh;
    yk[2] = yk[1] + f1 * invh;
    yk[3] = yk[2] + f2 * invh;
    yk[4] = yk[3] + f3 * invh;

    float dk[5];
    dk[0] = 1.0f;
    dk[1] = softplus_f(ud[0]);
    dk[2] = softplus_f(ud[1]);
    dk[3] = softplus_f(ud[2]);
    dk[4] = 1.0f;

    bool inside = (x >= -BOUND) && (x <= BOUND);
    float xc = fminf(fmaxf(x, -BOUND), BOUND);
    int idx = 0;
    if (xc >= xk[1]) idx = 1;
    if (xc >= xk[2]) idx = 2;
    if (xc >= xk[3]) idx = 3;

    float x0 = xk[idx], x1 = xk[idx + 1];
    float y0 = yk[idx], y1 = yk[idx + 1];
    float d0 = dk[idx], d1 = dk[idx + 1];
    float dx = x1 - x0, dy = y1 - y0;
    float s = __fdividef(dy, dx);
    float tt = __fdividef(xc - x0, dx);
    float omt = 1.0f - tt;
    float den = s + (d1 + d0 - 2.0f * s) * tt * omt;
    float y = y0 + __fdividef(dy * (s * tt * tt + d0 * tt * omt), den);
    float num = s * s * (d1 * tt * tt + 2.0f * s * tt * omt + d0 * omt * omt);
    float ld = __logf(num) - 2.0f * __logf(den);

    *ld_out = inside ? ld : 0.0f;
    return inside ? y : x;
}

// ---------------------------------------------------------------------------
// Latent head v6: 2 blocks per batch (32 sites x 4 lanes = 128 threads),
// pool3 fused, packed MLP, MUFU. KLD partial per half-batch -> g_kldp.
// ---------------------------------------------------------------------------
constexpr int LSITES = 32;   // sites per block
constexpr int LT = 128;      // threads per block

__global__ __launch_bounds__(LT) void latent_kernel(
    const float* __restrict__ y3,
    const unsigned char* __restrict__ m2,
    const float* __restrict__ eps,
    const float* __restrict__ wmu, const float* __restrict__ bmu,
    const float* __restrict__ wlv, const float* __restrict__ blv,
    const float* __restrict__ wlin, const float* __restrict__ blin,
    const float* __restrict__ fW1, const float* __restrict__ fb1,
    const float* __restrict__ fW2, const float* __restrict__ fb2,
    const float* __restrict__ fW3, const float* __restrict__ fb3,
    float* __restrict__ dec, float* __restrict__ dout,
    float* __restrict__ kldp)
{
    __shared__ __align__(16) float sW1[NT * HID * LAT];
    __shared__ __align__(16) float sW2[NT * HID * HID];
    __shared__ __align__(16) float sW3[NT * LAT * NPAR * HID];
    __shared__ float sb1[NT * HID];
    __shared__ float sb2[NT * HID];
    __shared__ float sb3[NT * LAT * NPAR];
    __shared__ float swmu[LAT * C3], swlv[LAT * C3], swlin[C3 * LAT];
    __shared__ float sbmu[LAT], sblv[LAT], sblin[C3];
    __shared__ float skld[LSITES];

    const int tid  = threadIdx.x;
    const int b    = blockIdx.x >> 1;
    const int half = blockIdx.x & 1;

    for (int i = tid; i < NT * HID * LAT; i += LT) {
        int j = i % LAT;
        int r = (i / LAT) % HID;
        int hd = r % 3 + 1;
        sW1[i] = fW1[i] * ((hd >= j + 1) ? 1.0f : 0.0f);
    }
    for (int i = tid; i < NT * HID * HID; i += LT) {
        int j = i % HID;
        int r = (i / HID) % HID;
        int hdi = r % 3 + 1, hdj = j % 3 + 1;
        sW2[i] = fW2[i] * ((hdi >= hdj) ? 1.0f : 0.0f);
    }
    for (int i = tid; i < NT * LAT * NPAR * HID; i += LT) {
        int c = i % HID;
        int r = (i / HID) % (LAT * NPAR);
        int deg = r / NPAR + 1;
        int hdc = c % 3 + 1;
        sW3[i] = fW3[i] * ((deg > hdc) ? 1.0f : 0.0f);
    }
    for (int i = tid; i < NT * HID; i += LT) { sb1[i] = fb1[i]; sb2[i] = fb2[i]; }
    for (int i = tid; i < NT * LAT * NPAR; i += LT) sb3[i] = fb3[i];
    for (int i = tid; i < LAT * C3; i += LT) { swmu[i] = wmu[i]; swlv[i] = wlv[i]; swlin[i] = wlin[i]; }
    if (tid < LAT) { sbmu[tid] = bmu[tid]; sblv[tid] = blv[tid]; }
    if (tid < C3) sblin[tid] = blin[tid];
    __syncthreads();

    const int lsite = tid / 4;                 // 0..31
    const int site  = half * LSITES + lsite;   // 0..63
    const int l     = tid % 4;
    const int lane  = tid % 32;
    const int lbase = lane & ~3;
    const int hh = site / W3, ww = site % W3;
    const long sm = (long)b * (H3 * W3) + site;

    // ---- fused pool3 ----
    const int ih0 = hh * 5, iw0 = ww * 2;
    bool wm[10];
    bool act = false;
    {
        const unsigned char* mb = m2 + (long)b * (H2 * W2);
#pragma unroll
        for (int ii = 0; ii < 5; ii++)
#pragma unroll
            for (int jj = 0; jj < 2; jj++) {
                bool m = mb[(long)(ih0 + ii) * W2 + iw0 + jj] != 0;
                wm[ii * 2 + jj] = m;
                act = act || m;
            }
    }

    float pooled[C3 / 4];
    {
        const float* yb = y3 + ((long)b * C3) * (H2 * W2);
#pragma unroll
        for (int k = 0; k < C3 / 4; k++) {
            int c = l * (C3 / 4) + k;
            float v = -1e30f;
            const float* yc = yb + (long)c * (H2 * W2);
#pragma unroll
            for (int ii = 0; ii < 5; ii++)
#pragma unroll
                for (int jj = 0; jj < 2; jj++) {
                    if (wm[ii * 2 + jj])
                        v = fmaxf(v, yc[(long)(ih0 + ii) * W2 + iw0 + jj]);
                }
            pooled[k] = act ? v : 0.0f;
        }
    }

    float mu_own, lv_own;
    {
        float pm[LAT], pl[LAT];
#pragma unroll
        for (int j = 0; j < LAT; j++) { pm[j] = 0.0f; pl[j] = 0.0f; }
#pragma unroll
        for (int k = 0; k < C3 / 4; k++) {
            int c = l * (C3 / 4) + k;
            float yv = pooled[k];
#pragma unroll
            for (int j = 0; j < LAT; j++) {
                pm[j] += yv * swmu[j * C3 + c];
                pl[j] += yv * swlv[j * C3 + c];
            }
        }
#pragma unroll
        for (int j = 0; j < LAT; j++) {
            pm[j] += __shfl_xor_sync(0xffffffffu, pm[j], 1);
            pm[j] += __shfl_xor_sync(0xffffffffu, pm[j], 2);
            pl[j] += __shfl_xor_sync(0xffffffffu, pl[j], 1);
            pl[j] += __shfl_xor_sync(0xffffffffu, pl[j], 2);
        }
        mu_own = act ? (pm[l] + sbmu[l]) : 0.0f;
        lv_own = act ? (pl[l] + sblv[l]) : 0.0f;
    }

    float e_own = eps[sm * LAT + l];
    float z_own = mu_own + e_own * __expf(0.5f * lv_own);

    float z[LAT];
#pragma unroll
    for (int j = 0; j < LAT; j++)
        z[j] = __shfl_sync(0xffffffffu, z_own, lbase + j);

    float ldt_own = 0.0f;
    for (int t = 0; t < NT; t++) {
        const float* W1t = sW1 + t * HID * LAT;
        const float* W2t = sW2 + t * HID * HID;
        const float* W3t = sW3 + t * LAT * NPAR * HID;
        const float* b1t = sb1 + t * HID;
        const float* b2t = sb2 + t * HID;
        const float* b3t = sb3 + t * LAT * NPAR;

        unsigned long long zp[LAT / 2];
        zp[0] = pack2(z[0], z[1]);
        zp[1] = pack2(z[2], z[3]);

        float h1[HID];
#pragma unroll
        for (int i = 0; i < HID; i++)
            h1[i] = fmaxf(dot_packed<LAT / 2>(W1t + i * LAT, zp, b1t[i]), 0.0f);

        unsigned long long h1p[HID / 2];
#pragma unroll
        for (int k = 0; k < HID / 2; k++) h1p[k] = pack2(h1[2 * k], h1[2 * k + 1]);

        float h2[HID];
#pragma unroll
        for (int i = 0; i < HID; i++)
            h2[i] = fmaxf(dot_packed<HID / 2>(W2t + i * HID, h1p, b2t[i]), 0.0f);

        unsigned long long h2p[HID / 2];
#pragma unroll
        for (int k = 0; k < HID / 2; k++) h2p[k] = pack2(h2[2 * k], h2[2 * k + 1]);

        float p[NPAR];
#pragma unroll
        for (int n = 0; n < NPAR; n++)
            p[n] = dot_packed<HID / 2>(W3t + (l * NPAR + n) * HID, h2p, b3t[l * NPAR + n]);

        float ld;
        float zn_own = rqs_scalar(z[l], p, p + 4, p + 8, &ld);
        ldt_own += ld;

        float znv[LAT];
#pragma unroll
        for (int j = 0; j < LAT; j++)
            znv[j] = __shfl_sync(0xffffffffu, zn_own, lbase + j);
        if (t < NT - 1) {
#pragma unroll
            for (int j = 0; j < LAT; j++) z[j] = znv[LAT - 1 - j];
        } else {
#pragma unroll
            for (int j = 0; j < LAT; j++) z[j] = znv[j];
        }
    }

    float zf_own = act ? z[l] : 0.0f;
    float zf[LAT];
#pragma unroll
    for (int j = 0; j < LAT; j++) zf[j] = act ? z[j] : 0.0f;

    float part = (-0.5f * e_own * e_own - 0.5f * lv_own - 0.5f * LOG2PI)
               - (-0.5f * zf_own * zf_own - 0.5f * LOG2PI)
               - ldt_own;
    part += __shfl_xor_sync(0xffffffffu, part, 1);
    part += __shfl_xor_sync(0xffffffffu, part, 2);

    dout[MU_OFF + sm * LAT + l] = mu_own;
    dout[LV_OFF + sm * LAT + l] = lv_own;
    dout[ZF_OFF + sm * LAT + l] = zf_own;

#pragma unroll
    for (int k = 0; k < C3 / 4; k++) {
        int c = l * (C3 / 4) + k;
        float d = 0.0f;
        if (act) {
            d = sblin[c];
#pragma unroll
            for (int j = 0; j < LAT; j++) d += zf[j] * swlin[c * LAT + j];
        }
        dec[(((long)b * C3 + c) * H3 + hh) * W3 + ww] = d;
    }

    // partial kld over this block's 32 sites
    if (l == 0) skld[lsite] = act ? part : 0.0f;
    __syncthreads();
    for (int off = LSITES / 2; off > 0; off >>= 1) {
        if (tid < off) skld[tid] += skld[tid + off];
        __syncthreads();
    }
    if (tid == 0) kldp[b * 2 + half] = skld[0];
}

// Tiny finisher: kld[b] = kldp[2b] + kldp[2b+1]
__global__ void kld_finish_kernel(const float* __restrict__ kldp, float* __restrict__ dout)
{
    int i = threadIdx.x;
    if (i < B) dout[KLD_OFF + i] = kldp[2 * i] + kldp[2 * i + 1];
}

// ---------------------------------------------------------------------------
// Host launcher
// ---------------------------------------------------------------------------
static void* sym_addr(const void* sym)
{
    void* p = nullptr;
    cudaGetSymbolAddress(&p, sym);
    return p;
}

extern "C" void kernel_launch(void* const* d_in, const int* in_sizes, int n_in,
                              void* d_out, int out_size)
{
    (void)in_sizes; (void)n_in; (void)out_size;

    const float* x    = (const float*)d_in[0];
    const float* eps  = (const float*)d_in[1];
    const float* w1   = (const float*)d_in[2];
    const float* b1   = (const float*)d_in[3];
    const float* w2   = (const float*)d_in[4];
    const float* b2   = (const float*)d_in[5];
    const float* w3   = (const float*)d_in[6];
    const float* b3   = (const float*)d_in[7];
    const float* wmu  = (const float*)d_in[8];
    const float* bmu  = (const float*)d_in[9];
    const float* wlv  = (const float*)d_in[10];
    const float* blv  = (const float*)d_in[11];
    const float* wlin = (const float*)d_in[12];
    const float* blin = (const float*)d_in[13];
    const float* u1   = (const float*)d_in[14];
    const float* bu1  = (const float*)d_in[15];
    const float* w4   = (const float*)d_in[16];
    const float* b4   = (const float*)d_in[17];
    const float* u2   = (const float*)d_in[18];
    const float* bu2  = (const float*)d_in[19];
    const float* w5   = (const float*)d_in[20];
    const float* b5   = (const float*)d_in[21];
    const float* u3   = (const float*)d_in[22];
    const float* bu3  = (const float*)d_in[23];
    const float* w6   = (const float*)d_in[24];
    const float* b6   = (const float*)d_in[25];
    const float* fW1  = (const float*)d_in[26];
    const float* fb1  = (const float*)d_in[27];
    const float* fW2  = (const float*)d_in[28];
    const float* fb2  = (const float*)d_in[29];
    const float* fW3  = (const float*)d_in[30];
    const float* fb3  = (const float*)d_in[31];
    float* out = (float*)d_out;

    float* p1   = (float*)sym_addr(g_p1);
    float* p2   = (float*)sym_addr(g_p2);
    float* y3   = (float*)sym_addr(g_y3);
    float* dec  = (float*)sym_addr(g_dec);
    float* d1   = (float*)sym_addr(g_d1);
    float* c4   = (float*)sym_addr(g_c4);
    float* c5   = (float*)sym_addr(g_c5);
    float* kldp = (float*)sym_addr(g_kldp);
    unsigned char* m0 = (unsigned char*)sym_addr(g_m0);
    unsigned char* m1 = (unsigned char*)sym_addr(g_m1);
    unsigned char* m2 = (unsigned char*)sym_addr(g_m2);

    // ---- encoder ----
    enc1_kernel<<<dim3(W0 / E1W, (H0 + E1H - 1) / E1H, B), E1T>>>(x, w1, b1, p1, m0, m1);

    conv2pool_kernel<<<dim3(W1 / P2TW, H1 / P2TH, B), P2T>>>(p1, m1, w2, b2, p2, m2);

    conv_tiled_kernel<C2, C3, 4, 32, 128, true>
        <<<dim3(W2 / 32, H2 / 4, B), 128>>>(p2, m2, w3, b3, y3, H2, W2);

    // ---- latent (pool3 fused; 2 blocks/batch) ----
    latent_kernel<<<B * 2, LT>>>(y3, m2, eps, wmu, bmu, wlv, blv, wlin, blin,
                                 fW1, fb1, fW2, fb2, fW3, fb3, dec, out, kldp);
    kld_finish_kernel<<<1, B>>>(kldp, out);

    // ---- decoder ----
    invconv_kernel<C3, C3, 5, 2, 128>
        <<<(unsigned)(((long)B * H2 * W2 + 127) / 128), 128>>>(dec, m2, u1, bu1, d1, H3, W3);
    conv_tiled_kernel<C3, C2, 4, 32, 128, false>
        <<<dim3(W2 / 32, H2 / 4, B), 128>>>(d1, m2, w4, b4, c4, H2, W2);

    dec_fused_kernel<C2, C2, C1, 5, 2, 8, 32, 128>
        <<<dim3(W1 / 32, (H1 + 7) / 8, B), 128>>>(c4, m1, u2, bu2, w5, b5, c5, H2, W2);

    dec_fused_kernel<C1, C1, C0, 2, 2, 16, 32, 128>
        <<<dim3(W0 / 32, (H0 + 15) / 16, B), 128>>>(c5, m0, u3, bu3, w6, b6, out, H1, W1);
}

// round 17
// speedup vs baseline: 1.0106x; 1.0106x over previous
#include <cuda_runtime.h>
#include <math.h>

// ---------------------------------------------------------------------------
// Problem dimensions (fixed by setup_inputs)
// ---------------------------------------------------------------------------
namespace cfg {
constexpr int B  = 128;
constexpr int H0 = 200, W0 = 128, C0 = 6;
constexpr int C1 = 8;
constexpr int H1 = 100, W1 = 64;
constexpr int C2 = 16;
constexpr int H2 = 20,  W2 = 32;
constexpr int C3 = 32;
constexpr int H3 = 4,   W3 = 16;
constexpr int LAT = 4, HID = 16, NPAR = 11, NT = 10;
constexpr float BOUND = 5.0f;
constexpr float LOG2PI = 1.8378770664093453f;

constexpr int NW1 = NT * HID * LAT;          //  640
constexpr int NW2 = NT * HID * HID;          // 2560
constexpr int NW3 = NT * LAT * NPAR * HID;   // 7040

constexpr long OUT_N   = (long)B * C0 * H0 * W0;
constexpr long MU_OFF  = OUT_N;
constexpr long MU_N    = (long)B * H3 * W3 * LAT;
constexpr long LV_OFF  = MU_OFF + MU_N;
constexpr long KLD_OFF = LV_OFF + MU_N;
constexpr long ZF_OFF  = KLD_OFF + B;
}
using namespace cfg;

// ---------------------------------------------------------------------------
// Packed f32x2 FMA helpers (Blackwell FFMA2)
// ---------------------------------------------------------------------------
__device__ __forceinline__ unsigned long long pack2(float lo, float hi)
{
    unsigned long long r;
    asm("mov.b64 %0, {%1, %2};" : "=l"(r) : "f"(lo), "f"(hi));
    return r;
}
__device__ __forceinline__ void unpack2(unsigned long long v, float& lo, float& hi)
{
    asm("mov.b64 {%0, %1}, %2;" : "=f"(lo), "=f"(hi) : "l"(v));
}
__device__ __forceinline__ unsigned long long ffma2(unsigned long long a,
                                                    unsigned long long b,
                                                    unsigned long long c)
{
    unsigned long long d;
    asm("fma.rn.f32x2 %0, %1, %2, %3;" : "=l"(d) : "l"(a), "l"(b), "l"(c));
    return d;
}

template <int CO>
__device__ __forceinline__ void fma_row2(const float* __restrict__ wrow, float v,
                                         unsigned long long* acc)
{
    unsigned long long vv = pack2(v, v);
#pragma unroll
    for (int g = 0; g < CO / 2; g++) {
        unsigned long long w = *reinterpret_cast<const unsigned long long*>(wrow + 2 * g);
        acc[g] = ffma2(vv, w, acc[g]);
    }
}

template <int P>
__device__ __forceinline__ void store_px(float* dst, const float* v)
{
    if constexpr (P == 4) {
        *reinterpret_cast<float4*>(dst) = make_float4(v[0], v[1], v[2], v[3]);
    } else if constexpr (P == 2) {
        *reinterpret_cast<float2*>(dst) = make_float2(v[0], v[1]);
    } else {
        dst[0] = v[0];
    }
}

template <int N2>
__device__ __forceinline__ float dot_packed(const float* __restrict__ row,
                                            const unsigned long long* xp, float bias)
{
    unsigned long long acc = pack2(bias, 0.0f);
    const unsigned long long* r2 = reinterpret_cast<const unsigned long long*>(row);
#pragma unroll
    for (int k = 0; k < N2; k++) acc = ffma2(xp[k], r2[k], acc);
    float lo, hi;
    unpack2(acc, lo, hi);
    return lo + hi;
}

// ---------------------------------------------------------------------------
// Static device scratch
// ---------------------------------------------------------------------------
__device__ float g_p1[(long)B * C1 * H1 * W1];
__device__ float g_p2[(long)B * C2 * H2 * W2];
__device__ float g_y3[(long)B * C3 * H2 * W2];
__device__ float g_dec[(long)B * C3 * H3 * W3];
__device__ float g_d1[(long)B * C3 * H2 * W2];
__device__ float g_c4[(long)B * C2 * H2 * W2];
__device__ float g_c5[(long)B * C1 * H1 * W1];
__device__ float g_fw1m[NW1];
__device__ float g_fw2m[NW2];
__device__ float g_fw3m[NW3];
__device__ unsigned char g_m0[(long)B * H0 * W0];
__device__ unsigned char g_m1[(long)B * H1 * W1];
__device__ unsigned char g_m2[(long)B * H2 * W2];

// ---------------------------------------------------------------------------
// One-shot: mask the flow weights into global scratch (tiny kernel)
// ---------------------------------------------------------------------------
__global__ void prep_weights_kernel(const float* __restrict__ fW1,
                                    const float* __restrict__ fW2,
                                    const float* __restrict__ fW3,
                                    float* __restrict__ w1m,
                                    float* __restrict__ w2m,
                                    float* __restrict__ w3m)
{
    int i = blockIdx.x * blockDim.x + threadIdx.x;
    if (i < NW1) {
        int j = i % LAT;
        int r = (i / LAT) % HID;
        int hd = r % 3 + 1;
        w1m[i] = fW1[i] * ((hd >= j + 1) ? 1.0f : 0.0f);
    }
    if (i < NW2) {
        int j = i % HID;
        int r = (i / HID) % HID;
        int hdi = r % 3 + 1, hdj = j % 3 + 1;
        w2m[i] = fW2[i] * ((hdi >= hdj) ? 1.0f : 0.0f);
    }
    if (i < NW3) {
        int c = i % HID;
        int r = (i / HID) % (LAT * NPAR);
        int deg = r / NPAR + 1;
        int hdc = c % 3 + 1;
        w3m[i] = fW3[i] * ((deg > hdc) ? 1.0f : 0.0f);
    }
}

// ---------------------------------------------------------------------------
// Fused encoder stage 1: mask0 + conv1(3x3, 6->8) + lrelu + maxpool 2x2 + m1
// ---------------------------------------------------------------------------
constexpr int E1H = 16, E1W = 32, E1T = 128;

__global__ __launch_bounds__(E1T) void enc1_kernel(
    const float* __restrict__ x, const float* __restrict__ w1,
    const float* __restrict__ b1, float* __restrict__ p1,
    unsigned char* __restrict__ m0, unsigned char* __restrict__ m1)
{
    __shared__ __align__(16) float xs[C0][E1H + 2][E1W + 2];
    __shared__ __align__(16) float cs[C1][E1H][E1W];
    __shared__ unsigned char ms[E1H][E1W];
    __shared__ __align__(16) float ws[9 * C0 * C1];
    __shared__ float bs[C1];

    const int b  = blockIdx.z;
    const int h0 = blockIdx.y * E1H;
    const int w0 = blockIdx.x * E1W;
    const int tid = threadIdx.x;

    for (int i = tid; i < 9 * C0 * C1; i += E1T) ws[i] = w1[i];
    if (tid < C1) bs[tid] = b1[tid];

    for (int i = tid; i < C0 * (E1H + 2) * (E1W + 2); i += E1T) {
        int lw = i % (E1W + 2);
        int r  = i / (E1W + 2);
        int lh = r % (E1H + 2);
        int c  = r / (E1H + 2);
        int gh = h0 + lh - 1, gw = w0 + lw - 1;
        float v = 0.0f;
        if (gh >= 0 && gh < H0 && gw >= 0 && gw < W0)
            v = x[(((long)b * C0 + c) * H0 + gh) * W0 + gw];
        xs[c][lh][lw] = v;
    }
    __syncthreads();

    {
        const int pix = tid * 4;
        const int lh = pix / E1W, lw = pix % E1W;
        const int gh = h0 + lh, gw = w0 + lw;

        bool a[4];
        bool anyA = false;
#pragma unroll
        for (int p = 0; p < 4; p++) {
            bool v = false;
            if (gh < H0) {
#pragma unroll
                for (int c = 0; c < C0; c++)
                    v = v || (xs[c][lh + 1][lw + 1 + p] != 0.0f);
            }
            a[p] = v;
            anyA = anyA || v;
            ms[lh][lw + p] = v ? 1 : 0;
        }
        if (gh < H0) {
            uchar4 mq = make_uchar4(a[0] ? 1 : 0, a[1] ? 1 : 0, a[2] ? 1 : 0, a[3] ? 1 : 0);
            *reinterpret_cast<uchar4*>(m0 + ((long)b * H0 + gh) * W0 + gw) = mq;
        }

        unsigned long long acc[4][C1 / 2];
#pragma unroll
        for (int p = 0; p < 4; p++)
#pragma unroll
            for (int g = 0; g < C1 / 2; g++)
                acc[p][g] = pack2(bs[2 * g], bs[2 * g + 1]);

        if (anyA) {
#pragma unroll
            for (int kh = 0; kh < 3; kh++)
#pragma unroll
                for (int ci = 0; ci < C0; ci++) {
                    float v[6];
#pragma unroll
                    for (int q = 0; q < 6; q++) v[q] = xs[ci][lh + kh][lw + q];
#pragma unroll
                    for (int kw = 0; kw < 3; kw++) {
                        const float* wrow = ws + ((kh * 3 + kw) * C0 + ci) * C1;
#pragma unroll
                        for (int p = 0; p < 4; p++)
                            fma_row2<C1>(wrow, v[kw + p], acc[p]);
                    }
                }
        }
#pragma unroll
        for (int g = 0; g < C1 / 2; g++)
#pragma unroll
            for (int p = 0; p < 4; p++) {
                float u0, u1;
                unpack2(acc[p][g], u0, u1);
                u0 = u0 > 0.0f ? u0 : 0.01f * u0;
                u1 = u1 > 0.0f ? u1 : 0.01f * u1;
                cs[2 * g][lh][lw + p]     = a[p] ? u0 : 0.0f;
                cs[2 * g + 1][lh][lw + p] = a[p] ? u1 : 0.0f;
            }
    }
    __syncthreads();

    {
        const int pw = tid % (E1W / 2), ph = tid / (E1W / 2);
        const int gph = h0 / 2 + ph, gpw = w0 / 2 + pw;
        if (gph < H1) {
            bool m00 = ms[2 * ph][2 * pw],     m01 = ms[2 * ph][2 * pw + 1];
            bool m10 = ms[2 * ph + 1][2 * pw], m11 = ms[2 * ph + 1][2 * pw + 1];
            bool any = m00 || m01 || m10 || m11;
            m1[((long)b * H1 + gph) * W1 + gpw] = any ? 1 : 0;
#pragma unroll
            for (int c = 0; c < C1; c++) {
                float v = -1e30f;
                if (m00) v = fmaxf(v, cs[c][2 * ph][2 * pw]);
                if (m01) v = fmaxf(v, cs[c][2 * ph][2 * pw + 1]);
                if (m10) v = fmaxf(v, cs[c][2 * ph + 1][2 * pw]);
                if (m11) v = fmaxf(v, cs[c][2 * ph + 1][2 * pw + 1]);
                p1[(((long)b * C1 + c) * H1 + gph) * W1 + gpw] = any ? v : 0.0f;
            }
        }
    }
}

// ---------------------------------------------------------------------------
// Fused conv2 (3x3, 8->16) + lrelu + maxpool 5x2 -> p2, m2
// ---------------------------------------------------------------------------
constexpr int P2TH = 10, P2TW = 32, P2T = 160;

__global__ __launch_bounds__(P2T) void conv2pool_kernel(
    const float* __restrict__ in, const unsigned char* __restrict__ m1,
    const float* __restrict__ wgt, const float* __restrict__ bias,
    float* __restrict__ p2, unsigned char* __restrict__ m2)
{
    __shared__ __align__(16) float xs[C1][P2TH + 2][P2TW + 2];
    __shared__ __align__(16) float cs[C2][P2TH][P2TW];
    __shared__ unsigned char ms[P2TH][P2TW];
    __shared__ __align__(16) float ws[9 * C1 * C2];
    __shared__ float bs[C2];

    const int b  = blockIdx.z;
    const int h0 = blockIdx.y * P2TH;
    const int w0 = blockIdx.x * P2TW;
    const int tid = threadIdx.x;

    for (int i = tid; i < 9 * C1 * C2; i += P2T) ws[i] = wgt[i];
    if (tid < C2) bs[tid] = bias[tid];

    for (int i = tid; i < C1 * (P2TH + 2) * (P2TW + 2); i += P2T) {
        int lw = i % (P2TW + 2);
        int r  = i / (P2TW + 2);
        int lh = r % (P2TH + 2);
        int c  = r / (P2TH + 2);
        int gh = h0 + lh - 1, gw = w0 + lw - 1;
        float v = 0.0f;
        if (gh >= 0 && gh < H1 && gw >= 0 && gw < W1)
            v = in[(((long)b * C1 + c) * H1 + gh) * W1 + gw];
        xs[c][lh][lw] = v;
    }
    __syncthreads();

    {
        const int pix = tid * 2;
        const int lh = pix / P2TW, lw = pix % P2TW;
        const int gh = h0 + lh, gw = w0 + lw;

        bool a[2];
        bool anyA = false;
#pragma unroll
        for (int p = 0; p < 2; p++) {
            a[p] = m1[((long)b * H1 + gh) * W1 + gw + p] != 0;
            anyA = anyA || a[p];
            ms[lh][lw + p] = a[p] ? 1 : 0;
        }

        unsigned long long acc[2][C2 / 2];
#pragma unroll
        for (int p = 0; p < 2; p++)
#pragma unroll
            for (int g = 0; g < C2 / 2; g++)
                acc[p][g] = pack2(bs[2 * g], bs[2 * g + 1]);

        if (anyA) {
#pragma unroll
            for (int kh = 0; kh < 3; kh++)
#pragma unroll
                for (int ci = 0; ci < C1; ci++) {
                    float v[4];
#pragma unroll
                    for (int q = 0; q < 4; q++) v[q] = xs[ci][lh + kh][lw + q];
#pragma unroll
                    for (int kw = 0; kw < 3; kw++) {
                        const float* wrow = ws + ((kh * 3 + kw) * C1 + ci) * C2;
#pragma unroll
                        for (int p = 0; p < 2; p++)
                            fma_row2<C2>(wrow, v[kw + p], acc[p]);
                    }
                }
        }
#pragma unroll
        for (int g = 0; g < C2 / 2; g++)
#pragma unroll
            for (int p = 0; p < 2; p++) {
                float u0, u1;
                unpack2(acc[p][g], u0, u1);
                u0 = u0 > 0.0f ? u0 : 0.01f * u0;
                u1 = u1 > 0.0f ? u1 : 0.01f * u1;
                cs[2 * g][lh][lw + p]     = a[p] ? u0 : 0.0f;
                cs[2 * g + 1][lh][lw + p] = a[p] ? u1 : 0.0f;
            }
    }
    __syncthreads();

    const int POOL_PX = (P2TH / 5) * (P2TW / 2);  // 32
    for (int i = tid; i < POOL_PX * C2; i += P2T) {
        int c  = i / POOL_PX;
        int px = i % POOL_PX;
        int ph = px / (P2TW / 2), pw = px % (P2TW / 2);
        bool any = false;
        float v = -1e30f;
#pragma unroll
        for (int ii = 0; ii < 5; ii++)
#pragma unroll
            for (int jj = 0; jj < 2; jj++) {
                if (ms[ph * 5 + ii][pw * 2 + jj]) {
                    any = true;
                    v = fmaxf(v, cs[c][ph * 5 + ii][pw * 2 + jj]);
                }
            }
        int gph = h0 / 5 + ph, gpw = w0 / 2 + pw;
        p2[(((long)b * C2 + c) * H2 + gph) * W2 + gpw] = any ? v : 0.0f;
        if (c == 0) m2[((long)b * H2 + gph) * W2 + gpw] = any ? 1 : 0;
    }
}

// ---------------------------------------------------------------------------
// Tiled 3x3 SAME conv (generic, dense mask), packed FFMA2, vector stores
// ---------------------------------------------------------------------------
template <int CI, int CO, int TH, int TW, int THREADS, bool LRELU>
__global__ __launch_bounds__(THREADS) void conv_tiled_kernel(
    const float* __restrict__ in, const unsigned char* __restrict__ mask,
    const float* __restrict__ wgt, const float* __restrict__ bias,
    float* __restrict__ out, int H, int W)
{
    constexpr int P = (TH * TW) / THREADS;
    static_assert(P == 1 || P == 2 || P == 4, "P must be 1/2/4");
    static_assert(CO % 2 == 0, "CO must be even");
    __shared__ __align__(16) float xs[CI][TH + 2][TW + 2];
    __shared__ __align__(16) float ws[9 * CI * CO];
    __shared__ float bs[CO];

    const int b  = blockIdx.z;
    const int h0 = blockIdx.y * TH;
    const int w0 = blockIdx.x * TW;
    const int tid = threadIdx.x;

    for (int i = tid; i < 9 * CI * CO; i += THREADS) ws[i] = wgt[i];
    if (tid < CO) bs[tid] = bias[tid];

    for (int i = tid; i < CI * (TH + 2) * (TW + 2); i += THREADS) {
        int lw = i % (TW + 2);
        int r  = i / (TW + 2);
        int lh = r % (TH + 2);
        int c  = r / (TH + 2);
        int gh = h0 + lh - 1, gw = w0 + lw - 1;
        float v = 0.0f;
        if (gh >= 0 && gh < H && gw >= 0 && gw < W)
            v = in[(((long)b * CI + c) * H + gh) * W + gw];
        xs[c][lh][lw] = v;
    }
    __syncthreads();

    const int pix = tid * P;
    const int lh = pix / TW, lw = pix % TW;
    const int gh = h0 + lh, gw = w0 + lw;

    bool a[P];
    bool anyA = false;
#pragma unroll
    for (int p = 0; p < P; p++) {
        a[p] = (gh < H) ? (mask[((long)b * H + gh) * W + gw + p] != 0) : false;
        anyA = anyA || a[p];
    }

    unsigned long long acc[P][CO / 2];
#pragma unroll
    for (int p = 0; p < P; p++)
#pragma unroll
        for (int g = 0; g < CO / 2; g++) acc[p][g] = pack2(bs[2 * g], bs[2 * g + 1]);

    if (anyA) {
#pragma unroll
        for (int kh = 0; kh < 3; kh++)
#pragma unroll
            for (int ci = 0; ci < CI; ci++) {
                float v[P + 2];
#pragma unroll
                for (int q = 0; q < P + 2; q++) v[q] = xs[ci][lh + kh][lw + q];
#pragma unroll
                for (int kw = 0; kw < 3; kw++) {
                    const float* wrow = ws + ((kh * 3 + kw) * CI + ci) * CO;
#pragma unroll
                    for (int p = 0; p < P; p++)
                        fma_row2<CO>(wrow, v[kw + p], acc[p]);
                }
            }
    }
    if (gh < H) {
#pragma unroll
        for (int g = 0; g < CO / 2; g++) {
            float lo[P], hi[P];
#pragma unroll
            for (int p = 0; p < P; p++) {
                float u0, u1;
                unpack2(acc[p][g], u0, u1);
                if (LRELU) {
                    u0 = u0 > 0.0f ? u0 : 0.01f * u0;
                    u1 = u1 > 0.0f ? u1 : 0.01f * u1;
                }
                lo[p] = a[p] ? u0 : 0.0f;
                hi[p] = a[p] ? u1 : 0.0f;
            }
            store_px<P>(&out[(((long)b * CO + 2 * g) * H + gh) * W + gw], lo);
            store_px<P>(&out[(((long)b * CO + 2 * g + 1) * H + gh) * W + gw], hi);
        }
    }
}

// ---------------------------------------------------------------------------
// Fused decoder stage: invconv (KHxKW upsample, CI->CM) + 3x3 conv (CM->CO)
// ---------------------------------------------------------------------------
template <int CI, int CM, int CO, int KH, int KW, int TH, int TW, int THREADS>
__global__ __launch_bounds__(THREADS) void dec_fused_kernel(
    const float* __restrict__ in, const unsigned char* __restrict__ mo,
    const float* __restrict__ u, const float* __restrict__ bu,
    const float* __restrict__ wgt, const float* __restrict__ bias,
    float* __restrict__ out, int Hi, int Wi)
{
    constexpr int P = (TH * TW) / THREADS;
    static_assert(P == 1 || P == 2 || P == 4, "P must be 1/2/4");
    static_assert(CM % 2 == 0 && CO % 2 == 0, "CM/CO must be even");
    const int Ho = Hi * KH, Wo = Wi * KW;

    __shared__ __align__(16) float us_[CM][TH + 2][TW + 2];
    __shared__ unsigned char msk[(TH + 2) * (TW + 2)];
    __shared__ __align__(16) float su[KH * KW * CI * CM];
    __shared__ __align__(16) float ws[9 * CM * CO];
    __shared__ float sbu[CM], bs[CO];

    const int b  = blockIdx.z;
    const int h0 = blockIdx.y * TH;
    const int w0 = blockIdx.x * TW;
    const int tid = threadIdx.x;

    for (int i = tid; i < KH * KW * CI * CM; i += THREADS) su[i] = u[i];
    for (int i = tid; i < 9 * CM * CO; i += THREADS) ws[i] = wgt[i];
    if (tid < CM) sbu[tid] = bu[tid];
    if (tid < CO) bs[tid] = bias[tid];
    __syncthreads();

    for (int i = tid; i < (TH + 2) * (TW + 2); i += THREADS) {
        int lw = i % (TW + 2), lh = i / (TW + 2);
        int gh = h0 + lh - 1, gw = w0 + lw - 1;
        bool act = false;
        if (gh >= 0 && gh < Ho && gw >= 0 && gw < Wo)
            act = mo[((long)b * Ho + gh) * Wo + gw] != 0;
        unsigned long long val[CM / 2];
        if (act) {
#pragma unroll
            for (int g = 0; g < CM / 2; g++) val[g] = pack2(sbu[2 * g], sbu[2 * g + 1]);
            int hi = gh / KH, ii = gh % KH;
            int wi = gw / KW, jj = gw % KW;
            const float* ub = su + ((ii * KW + jj) * CI) * CM;
#pragma unroll
            for (int ci = 0; ci < CI; ci++) {
                float v = in[(((long)b * CI + ci) * Hi + hi) * Wi + wi];
                fma_row2<CM>(ub + ci * CM, v, val);
            }
        } else {
#pragma unroll
            for (int g = 0; g < CM / 2; g++) val[g] = 0ull;
        }
        msk[i] = act ? 1 : 0;
#pragma unroll
        for (int g = 0; g < CM / 2; g++) {
            float u0, u1;
            unpack2(val[g], u0, u1);
            us_[2 * g][lh][lw]     = u0;
            us_[2 * g + 1][lh][lw] = u1;
        }
    }
    __syncthreads();

    const int pix = tid * P;
    const int lh = pix / TW, lw = pix % TW;
    const int gh = h0 + lh, gw = w0 + lw;

    bool a[P];
    bool anyA = false;
#pragma unroll
    for (int p = 0; p < P; p++) {
        a[p] = (gh < Ho) && (msk[(lh + 1) * (TW + 2) + lw + 1 + p] != 0);
        anyA = anyA || a[p];
    }

    unsigned long long acc[P][CO / 2];
#pragma unroll
    for (int p = 0; p < P; p++)
#pragma unroll
        for (int g = 0; g < CO / 2; g++) acc[p][g] = pack2(bs[2 * g], bs[2 * g + 1]);

    if (anyA) {
#pragma unroll
        for (int kh = 0; kh < 3; kh++)
#pragma unroll
            for (int ci = 0; ci < CM; ci++) {
                float v[P + 2];
#pragma unroll
                for (int q = 0; q < P + 2; q++) v[q] = us_[ci][lh + kh][lw + q];
#pragma unroll
                for (int kw = 0; kw < 3; kw++) {
                    const float* wrow = ws + ((kh * 3 + kw) * CM + ci) * CO;
#pragma unroll
                    for (int p = 0; p < P; p++)
                        fma_row2<CO>(wrow, v[kw + p], acc[p]);
                }
            }
    }
    if (gh < Ho) {
#pragma unroll
        for (int g = 0; g < CO / 2; g++) {
            float lo[P], hi[P];
#pragma unroll
            for (int p = 0; p < P; p++) {
                float u0, u1;
                unpack2(acc[p][g], u0, u1);
                lo[p] = a[p] ? u0 : 0.0f;
                hi[p] = a[p] ? u1 : 0.0f;
            }
            store_px<P>(&out[(((long)b * CO + 2 * g) * Ho + gh) * Wo + gw], lo);
            store_px<P>(&out[(((long)b * CO + 2 * g + 1) * Ho + gh) * Wo + gw], hi);
        }
    }
}

// ---------------------------------------------------------------------------
// Standalone inverse conv (dec1 only), packed FFMA2
// ---------------------------------------------------------------------------
template <int CI, int CO, int KH, int KW, int THREADS>
__global__ __launch_bounds__(THREADS) void invconv_kernel(
    const float* __restrict__ in, const unsigned char* __restrict__ mask,
    const float* __restrict__ wgt, const float* __restrict__ bias,
    float* __restrict__ out, int Hi, int Wi)
{
    static_assert(CO % 2 == 0, "CO even");
    __shared__ __align__(16) float ws[KH * KW * CI * CO];
    __shared__ float bs[CO];
    for (int i = threadIdx.x; i < KH * KW * CI * CO; i += THREADS) ws[i] = wgt[i];
    for (int i = threadIdx.x; i < CO; i += THREADS) bs[i] = bias[i];
    __syncthreads();

    const int Ho = Hi * KH, Wo = Wi * KW;
    long idx = (long)blockIdx.x * blockDim.x + threadIdx.x;
    long total = (long)B * Ho * Wo;
    if (idx >= total) return;
    int wo = (int)(idx % Wo);
    long t = idx / Wo;
    int ho = (int)(t % Ho);
    int b  = (int)(t / Ho);

    long oplane = (long)Ho * Wo;
    unsigned long long acc[CO / 2];
    bool act = mask[idx] != 0;
    if (act) {
#pragma unroll
        for (int g = 0; g < CO / 2; g++) acc[g] = pack2(bs[2 * g], bs[2 * g + 1]);
        int hi = ho / KH, i = ho % KH;
        int wi = wo / KW, j = wo % KW;
        const float* ws2 = ws + (i * KW + j) * CI * CO;
        long iplane = (long)Hi * Wi;
        const float* inb = in + (long)b * CI * iplane + (long)hi * Wi + wi;
#pragma unroll
        for (int ci = 0; ci < CI; ci++) {
            float v = inb[(long)ci * iplane];
            fma_row2<CO>(ws2 + ci * CO, v, acc);
        }
    } else {
#pragma unroll
        for (int g = 0; g < CO / 2; g++) acc[g] = 0ull;
    }
    float* outb = out + (long)b * CO * oplane + (long)ho * Wo + wo;
#pragma unroll
    for (int g = 0; g < CO / 2; g++) {
        float u0, u1;
        unpack2(acc[g], u0, u1);
        outb[(long)(2 * g) * oplane]     = u0;
        outb[(long)(2 * g + 1) * oplane] = u1;
    }
}

// ---------------------------------------------------------------------------
// RQS spline — fast MUFU intrinsics
// ---------------------------------------------------------------------------
__device__ __forceinline__ float softplus_f(float x)
{
    return fmaxf(x, 0.0f) + __logf(1.0f + __expf(-fabsf(x)));
}

__device__ __forceinline__ float rqs_scalar(float x, const float* uw, const float* uh,
                                            const float* ud, float* ld_out)
{
    float mw = fmaxf(fmaxf(uw[0], uw[1]), fmaxf(uw[2], uw[3]));
    float e0 = __expf(uw[0] - mw), e1 = __expf(uw[1] - mw), e2 = __expf(uw[2] - mw), e3 = __expf(uw[3] - mw);
    float inv = __fdividef(2.0f * BOUND, e0 + e1 + e2 + e3);
    float xk[5];
    xk[0] = -BOUND;
    xk[1] = xk[0] + e0 * inv;
    xk[2] = xk[1] + e1 * inv;
    xk[3] = xk[2] + e2 * inv;
    xk[4] = xk[3] + e3 * inv;

    float mh = fmaxf(fmaxf(uh[0], uh[1]), fmaxf(uh[2], uh[3]));
    float f0 = __expf(uh[0] - mh), f1 = __expf(uh[1] - mh), f2 = __expf(uh[2] - mh), f3 = __expf(uh[3] - mh);
    float invh = __fdividef(2.0f * BOUND, f0 + f1 + f2 + f3);
    float yk[5];
    yk[0] = -BOUND;
    yk[1] = yk[0] + f0 * invh;
    yk[2] = yk[1] + f1 * invh;
    yk[3] = yk[2] + f2 * invh;
    yk[4] = yk[3] + f3 * invh;

    float dk[5];
    dk[0] = 1.0f;
    dk[1] = softplus_f(ud[0]);
    dk[2] = softplus_f(ud[1]);
    dk[3] = softplus_f(ud[2]);
    dk[4] = 1.0f;

    bool inside = (x >= -BOUND) && (x <= BOUND);
    float xc = fminf(fmaxf(x, -BOUND), BOUND);
    int idx = 0;
    if (xc >= xk[1]) idx = 1;
    if (xc >= xk[2]) idx = 2;
    if (xc >= xk[3]) idx = 3;

    float x0 = xk[idx], x1 = xk[idx + 1];
    float y0 = yk[idx], y1 = yk[idx + 1];
    float d0 = dk[idx], d1 = dk[idx + 1];
    float dx = x1 - x0, dy = y1 - y0;
    float s = __fdividef(dy, dx);
    float tt = __fdividef(xc - x0, dx);
    float omt = 1.0f - tt;
    float den = s + (d1 + d0 - 2.0f * s) * tt * omt;
    float y = y0 + __fdividef(dy * (s * tt * tt + d0 * tt * omt), den);
    float num = s * s * (d1 * tt * tt + 2.0f * s * tt * omt + d0 * omt * omt);
    float ld = __logf(num) - 2.0f * __logf(den);

    *ld_out = inside ? ld : 0.0f;
    return inside ? y : x;
}

// ---------------------------------------------------------------------------
// Latent head v7: R15 shape (256 thr, grid B, pool3 fused), but weights are
// pre-masked in global scratch -> staging is a pure float4 copy.
// ---------------------------------------------------------------------------
__global__ __launch_bounds__(256) void latent_kernel(
    const float* __restrict__ y3,
    const unsigned char* __restrict__ m2,
    const float* __restrict__ eps,
    const float* __restrict__ wmu, const float* __restrict__ bmu,
    const float* __restrict__ wlv, const float* __restrict__ blv,
    const float* __restrict__ wlin, const float* __restrict__ blin,
    const float* __restrict__ w1m, const float* __restrict__ fb1,
    const float* __restrict__ w2m, const float* __restrict__ fb2,
    const float* __restrict__ w3m, const float* __restrict__ fb3,
    float* __restrict__ dec, float* __restrict__ dout)
{
    __shared__ __align__(16) float sW1[NW1];
    __shared__ __align__(16) float sW2[NW2];
    __shared__ __align__(16) float sW3[NW3];
    __shared__ float sb1[NT * HID];
    __shared__ float sb2[NT * HID];
    __shared__ float sb3[NT * LAT * NPAR];
    __shared__ float swmu[LAT * C3], swlv[LAT * C3], swlin[C3 * LAT];
    __shared__ float sbmu[LAT], sblv[LAT], sblin[C3];
    __shared__ float skld[64];

    const int tid = threadIdx.x;
    const int b = blockIdx.x;
    const int THREADS = 256;

    // pure vector-copy staging (weights pre-masked by prep kernel)
    for (int i = tid; i < NW1 / 4; i += THREADS)
        reinterpret_cast<float4*>(sW1)[i] = reinterpret_cast<const float4*>(w1m)[i];
    for (int i = tid; i < NW2 / 4; i += THREADS)
        reinterpret_cast<float4*>(sW2)[i] = reinterpret_cast<const float4*>(w2m)[i];
    for (int i = tid; i < NW3 / 4; i += THREADS)
        reinterpret_cast<float4*>(sW3)[i] = reinterpret_cast<const float4*>(w3m)[i];
    for (int i = tid; i < NT * HID; i += THREADS) { sb1[i] = fb1[i]; sb2[i] = fb2[i]; }
    for (int i = tid; i < NT * LAT * NPAR; i += THREADS) sb3[i] = fb3[i];
    for (int i = tid; i < LAT * C3; i += THREADS) { swmu[i] = wmu[i]; swlv[i] = wlv[i]; swlin[i] = wlin[i]; }
    if (tid < LAT) { sbmu[tid] = bmu[tid]; sblv[tid] = blv[tid]; }
    if (tid < C3) sblin[tid] = blin[tid];
    __syncthreads();

    const int site = tid / 4;
    const int l    = tid % 4;
    const int lane = tid % 32;
    const int lbase = lane & ~3;
    const int hh = site / W3, ww = site % W3;
    const long sm = (long)b * (H3 * W3) + site;

    // ---- fused pool3 ----
    const int ih0 = hh * 5, iw0 = ww * 2;
    bool wm[10];
    bool act = false;
    {
        const unsigned char* mb = m2 + (long)b * (H2 * W2);
#pragma unroll
        for (int ii = 0; ii < 5; ii++)
#pragma unroll
            for (int jj = 0; jj < 2; jj++) {
                bool m = mb[(long)(ih0 + ii) * W2 + iw0 + jj] != 0;
                wm[ii * 2 + jj] = m;
                act = act || m;
            }
    }

    float pooled[C3 / 4];
    {
        const float* yb = y3 + ((long)b * C3) * (H2 * W2);
#pragma unroll
        for (int k = 0; k < C3 / 4; k++) {
            int c = l * (C3 / 4) + k;
            float v = -1e30f;
            const float* yc = yb + (long)c * (H2 * W2);
#pragma unroll
            for (int ii = 0; ii < 5; ii++)
#pragma unroll
                for (int jj = 0; jj < 2; jj++) {
                    if (wm[ii * 2 + jj])
                        v = fmaxf(v, yc[(long)(ih0 + ii) * W2 + iw0 + jj]);
                }
            pooled[k] = act ? v : 0.0f;
        }
    }

    float mu_own, lv_own;
    {
        float pm[LAT], pl[LAT];
#pragma unroll
        for (int j = 0; j < LAT; j++) { pm[j] = 0.0f; pl[j] = 0.0f; }
#pragma unroll
        for (int k = 0; k < C3 / 4; k++) {
            int c = l * (C3 / 4) + k;
            float yv = pooled[k];
#pragma unroll
            for (int j = 0; j < LAT; j++) {
                pm[j] += yv * swmu[j * C3 + c];
                pl[j] += yv * swlv[j * C3 + c];
            }
        }
#pragma unroll
        for (int j = 0; j < LAT; j++) {
            pm[j] += __shfl_xor_sync(0xffffffffu, pm[j], 1);
            pm[j] += __shfl_xor_sync(0xffffffffu, pm[j], 2);
            pl[j] += __shfl_xor_sync(0xffffffffu, pl[j], 1);
            pl[j] += __shfl_xor_sync(0xffffffffu, pl[j], 2);
        }
        mu_own = act ? (pm[l] + sbmu[l]) : 0.0f;
        lv_own = act ? (pl[l] + sblv[l]) : 0.0f;
    }

    float e_own = eps[sm * LAT + l];
    float z_own = mu_own + e_own * __expf(0.5f * lv_own);

    float z[LAT];
#pragma unroll
    for (int j = 0; j < LAT; j++)
        z[j] = __shfl_sync(0xffffffffu, z_own, lbase + j);

    float ldt_own = 0.0f;
    for (int t = 0; t < NT; t++) {
        const float* W1t = sW1 + t * HID * LAT;
        const float* W2t = sW2 + t * HID * HID;
        const float* W3t = sW3 + t * LAT * NPAR * HID;
        const float* b1t = sb1 + t * HID;
        const float* b2t = sb2 + t * HID;
        const float* b3t = sb3 + t * LAT * NPAR;

        unsigned long long zp[LAT / 2];
        zp[0] = pack2(z[0], z[1]);
        zp[1] = pack2(z[2], z[3]);

        float h1[HID];
#pragma unroll
        for (int i = 0; i < HID; i++)
            h1[i] = fmaxf(dot_packed<LAT / 2>(W1t + i * LAT, zp, b1t[i]), 0.0f);

        unsigned long long h1p[HID / 2];
#pragma unroll
        for (int k = 0; k < HID / 2; k++) h1p[k] = pack2(h1[2 * k], h1[2 * k + 1]);

        float h2[HID];
#pragma unroll
        for (int i = 0; i < HID; i++)
            h2[i] = fmaxf(dot_packed<HID / 2>(W2t + i * HID, h1p, b2t[i]), 0.0f);

        unsigned long long h2p[HID / 2];
#pragma unroll
        for (int k = 0; k < HID / 2; k++) h2p[k] = pack2(h2[2 * k], h2[2 * k + 1]);

        float p[NPAR];
#pragma unroll
        for (int n = 0; n < NPAR; n++)
            p[n] = dot_packed<HID / 2>(W3t + (l * NPAR + n) * HID, h2p, b3t[l * NPAR + n]);

        float ld;
        float zn_own = rqs_scalar(z[l], p, p + 4, p + 8, &ld);
        ldt_own += ld;

        float znv[LAT];
#pragma unroll
        for (int j = 0; j < LAT; j++)
            znv[j] = __shfl_sync(0xffffffffu, zn_own, lbase + j);
        if (t < NT - 1) {
#pragma unroll
            for (int j = 0; j < LAT; j++) z[j] = znv[LAT - 1 - j];
        } else {
#pragma unroll
            for (int j = 0; j < LAT; j++) z[j] = znv[j];
        }
    }

    float zf_own = act ? z[l] : 0.0f;
    float zf[LAT];
#pragma unroll
    for (int j = 0; j < LAT; j++) zf[j] = act ? z[j] : 0.0f;

    float part = (-0.5f * e_own * e_own - 0.5f * lv_own - 0.5f * LOG2PI)
               - (-0.5f * zf_own * zf_own - 0.5f * LOG2PI)
               - ldt_own;
    part += __shfl_xor_sync(0xffffffffu, part, 1);
    part += __shfl_xor_sync(0xffffffffu, part, 2);

    dout[MU_OFF + sm * LAT + l] = mu_own;
    dout[LV_OFF + sm * LAT + l] = lv_own;
    dout[ZF_OFF + sm * LAT + l] = zf_own;

#pragma unroll
    for (int k = 0; k < C3 / 4; k++) {
        int c = l * (C3 / 4) + k;
        float d = 0.0f;
        if (act) {
            d = sblin[c];
#pragma unroll
            for (int j = 0; j < LAT; j++) d += zf[j] * swlin[c * LAT + j];
        }
        dec[(((long)b * C3 + c) * H3 + hh) * W3 + ww] = d;
    }

    if (l == 0) skld[site] = act ? part : 0.0f;
    __syncthreads();
    for (int off = 32; off > 0; off >>= 1) {
        if (tid < off) skld[tid] += skld[tid + off];
        __syncthreads();
    }
    if (tid == 0) dout[KLD_OFF + b] = skld[0];
}

// ---------------------------------------------------------------------------
// Host launcher
// ---------------------------------------------------------------------------
static void* sym_addr(const void* sym)
{
    void* p = nullptr;
    cudaGetSymbolAddress(&p, sym);
    return p;
}

extern "C" void kernel_launch(void* const* d_in, const int* in_sizes, int n_in,
                              void* d_out, int out_size)
{
    (void)in_sizes; (void)n_in; (void)out_size;

    const float* x    = (const float*)d_in[0];
    const float* eps  = (const float*)d_in[1];
    const float* w1   = (const float*)d_in[2];
    const float* b1   = (const float*)d_in[3];
    const float* w2   = (const float*)d_in[4];
    const float* b2   = (const float*)d_in[5];
    const float* w3   = (const float*)d_in[6];
    const float* b3   = (const float*)d_in[7];
    const float* wmu  = (const float*)d_in[8];
    const float* bmu  = (const float*)d_in[9];
    const float* wlv  = (const float*)d_in[10];
    const float* blv  = (const float*)d_in[11];
    const float* wlin = (const float*)d_in[12];
    const float* blin = (const float*)d_in[13];
    const float* u1   = (const float*)d_in[14];
    const float* bu1  = (const float*)d_in[15];
    const float* w4   = (const float*)d_in[16];
    const float* b4   = (const float*)d_in[17];
    const float* u2   = (const float*)d_in[18];
    const float* bu2  = (const float*)d_in[19];
    const float* w5   = (const float*)d_in[20];
    const float* b5   = (const float*)d_in[21];
    const float* u3   = (const float*)d_in[22];
    const float* bu3  = (const float*)d_in[23];
    const float* w6   = (const float*)d_in[24];
    const float* b6   = (const float*)d_in[25];
    const float* fW1  = (const float*)d_in[26];
    const float* fb1  = (const float*)d_in[27];
    const float* fW2  = (const float*)d_in[28];
    const float* fb2  = (const float*)d_in[29];
    const float* fW3  = (const float*)d_in[30];
    const float* fb3  = (const float*)d_in[31];
    float* out = (float*)d_out;

    float* p1   = (float*)sym_addr(g_p1);
    float* p2   = (float*)sym_addr(g_p2);
    float* y3   = (float*)sym_addr(g_y3);
    float* dec  = (float*)sym_addr(g_dec);
    float* d1   = (float*)sym_addr(g_d1);
    float* c4   = (float*)sym_addr(g_c4);
    float* c5   = (float*)sym_addr(g_c5);
    float* w1m  = (float*)sym_addr(g_fw1m);
    float* w2m  = (float*)sym_addr(g_fw2m);
    float* w3m  = (float*)sym_addr(g_fw3m);
    unsigned char* m0 = (unsigned char*)sym_addr(g_m0);
    unsigned char* m1 = (unsigned char*)sym_addr(g_m1);
    unsigned char* m2 = (unsigned char*)sym_addr(g_m2);

    // ---- weight prep (tiny; masks flow weights once) ----
    prep_weights_kernel<<<(NW3 + 255) / 256, 256>>>(fW1, fW2, fW3, w1m, w2m, w3m);

    // ---- encoder ----
    enc1_kernel<<<dim3(W0 / E1W, (H0 + E1H - 1) / E1H, B), E1T>>>(x, w1, b1, p1, m0, m1);

    conv2pool_kernel<<<dim3(W1 / P2TW, H1 / P2TH, B), P2T>>>(p1, m1, w2, b2, p2, m2);

    conv_tiled_kernel<C2, C3, 4, 32, 128, true>
        <<<dim3(W2 / 32, H2 / 4, B), 128>>>(p2, m2, w3, b3, y3, H2, W2);

    // ---- latent (pool3 fused; pre-masked weights) ----
    latent_kernel<<<B, 256>>>(y3, m2, eps, wmu, bmu, wlv, blv, wlin, blin,
                              w1m, fb1, w2m, fb2, w3m, fb3, dec, out);

    // ---- decoder ----
    invconv_kernel<C3, C3, 5, 2, 128>
        <<<(unsigned)(((long)B * H2 * W2 + 127) / 128), 128>>>(dec, m2, u1, bu1, d1, H3, W3);
    conv_tiled_kernel<C3, C2, 4, 32, 128, false>
        <<<dim3(W2 / 32, H2 / 4, B), 128>>>(d1, m2, w4, b4, c4, H2, W2);

    dec_fused_kernel<C2, C2, C1, 5, 2, 8, 32, 128>
        <<<dim3(W1 / 32, (H1 + 7) / 8, B), 128>>>(c4, m1, u2, bu2, w5, b5, c5, H2, W2);

    dec_fused_kernel<C1, C1, C0, 2, 2, 16, 32, 128>
        <<<dim3(W0 / 32, (H0 + 15) / 16, B), 128>>>(c5, m0, u3, bu3, w6, b6, out, H1, W1);
}